// round 9
// baseline (speedup 1.0000x reference)
#include <cuda_runtime.h>

#define NB 48
#define NL 17
#define ND 256
#define NM 768    /* NB*(L-1) */
#define NR 832    /* NM + NB anchors = 13*64 */
#define NTILES 90 /* 78 upper-tri tok tiles + 12 anchor-row tiles */
#define NBLK 296  /* 2 CTAs/SM on 148 SMs -> all co-resident */
#define NTASK 977 /* 816 norm + 16 pad + 144 pair-build + 1 scalars */

#define SCALE_C  4294967296.0f           /* 2^32 for csum fixed-point */
#define SCALE_KL 1.125899906842624e15f   /* 2^50 for kl fixed-point */

__device__ float g_all [NR*ND];   // rows 0..767 toks, 768..815 anchors, 816..831 zero
__device__ float g_E   [NR*NM];   // exp(sims): rows 0..767 Et (symmetric), 768..815 Ea
__device__ float g_nneg[NB];
__device__ float g_P   [NB];
__device__ int   g_pairs[NB*NM];  // (b<<16)|j, unordered (consumers are order-free)
__device__ unsigned int       g_pcnt;        // all counters zero-init; reset by final block
__device__ unsigned int       g_bar;
__device__ unsigned int       g_done;
__device__ unsigned long long g_csum  [NB];  // sum_neg Ea[b,k] * 2^32
__device__ unsigned long long g_rowsum[NB];  // sum_j kl[b,j]   * 2^50

// ---------------------------------------------------------------- utilities
__device__ __forceinline__ float blockReduceSum(float v, volatile float* sm) {
    int lane = threadIdx.x & 31, wid = threadIdx.x >> 5;
    #pragma unroll
    for (int o = 16; o > 0; o >>= 1) v += __shfl_down_sync(0xffffffffu, v, o);
    if (lane == 0) sm[wid] = v;
    __syncthreads();
    if (threadIdx.x < 32) {
        float r = (threadIdx.x < 8) ? sm[threadIdx.x] : 0.f;
        #pragma unroll
        for (int o = 4; o > 0; o >>= 1) r += __shfl_down_sync(0xffffffffu, r, o);
        if (threadIdx.x == 0) sm[0] = r;
    }
    __syncthreads();
    float r = sm[0];
    __syncthreads();
    return r;
}

// all-resident grid barrier (296 blocks, spin with sleep backoff)
__device__ __forceinline__ void grid_sync(unsigned int target) {
    __threadfence();
    __syncthreads();
    if (threadIdx.x == 0) {
        atomicAdd(&g_bar, 1u);
        while (*(volatile unsigned int*)&g_bar < target) __nanosleep(64);
    }
    __syncthreads();
    __threadfence();
}

// Reference declares int64 labels; jax w/o x64 silently yields int32. An
// int64 buffer (values 0..7, little-endian) read as int32 is [v,0,v,0,...].
__device__ __forceinline__ void load_labels(const int* __restrict__ lab32,
                                            int* lab, int* flag) {
    int t = threadIdx.x;
    if (t == 0) {
        bool is64 = true;
        for (int i = 1; i < NB; i += 2) if (lab32[i] != 0) { is64 = false; break; }
        if (is64) for (int i = 0; i < NB; i += 2) {
            int v = lab32[i];
            if (v < 0 || v >= 8) { is64 = false; break; }
        }
        *flag = is64 ? 1 : 0;
    }
    __syncthreads();
    if (t < NB) lab[t] = (*flag) ? (int)((const long long*)lab32)[t] : lab32[t];
    __syncthreads();
}

// =============================== the whole loss, one persistent kernel
__global__ void __launch_bounds__(256, 2)
k_fused(const float* __restrict__ x, const int* __restrict__ lab32,
        float* __restrict__ out) {
    __shared__ float sbuf[2 * 64 * 33];   // gemm tiles / transpose buffer
    __shared__ int   lab[NB];
    __shared__ int   flag;
    __shared__ float red[32];
    __shared__ unsigned int ticket_s;
    int bid = blockIdx.x, t = threadIdx.x;
    int tx = t & 15, ty = t >> 4, lane = t & 31, w = t >> 5;

    load_labels(lab32, lab, &flag);

    // ---------------- phase 0: norm rows / pad / pair list / scalars
    for (int task = bid; task < NTASK; task += NBLK) {
        if (task < NB * NL) {             // normalize input row
            float v = x[task * ND + t];
            float ss = blockReduceSum(v * v, red);
            float inv = 1.f / fmaxf(sqrtf(ss), 1e-12f);
            float xn = v * inv;
            int b = task / NL, p = task - b * NL;
            int row = (p == 0) ? (NM + b) : (b * (NL - 1) + p - 1);
            g_all[row * ND + t] = xn;
        } else if (task < NR) {           // zero pad rows 816..831
            g_all[task * ND + t] = 0.f;
        } else if (task < NTASK - 1) {    // pair list (unordered atomic append)
            int p = (task - NR) * 256 + t;       // 0..36863
            int b = p / NM, j = p - b * NM;
            if (lab[j >> 4] == lab[b]) {
                unsigned pos = atomicAdd(&g_pcnt, 1u);
                g_pairs[pos] = (b << 16) | j;
            }
        } else if (t < NB) {              // per-b scalars
            int same = 0;
            #pragma unroll 8
            for (int o = 0; o < NB; o++) same += (lab[o] == lab[t]) ? 1 : 0;
            g_nneg[t] = (float)((NB - same) * (NL - 1));
            g_P[t]    = (float)(same * (NL - 1));
        }
    }

    grid_sync(NBLK);

    // ---------------- phase 1: symmetric GEMM + exp epilogue (+csum on anchors)
    for (int id = bid; id < NTILES; id += NBLK) {
        int jt, kt;
        if (id < 78) {
            jt = 0; int rem = id;
            while (rem >= 12 - jt) { rem -= 12 - jt; jt++; }
            kt = jt + rem;
        } else { jt = 12; kt = id - 78; }
        int jb = jt * 64, kb = kt * 64;
        float* As = sbuf;
        float* Bs = sbuf + 64 * 33;

        float4 pa[2], pb[2];
        #pragma unroll
        for (int u = 0; u < 2; u++) {
            int idx = t + u * 256, row = idx >> 3, c4 = (idx & 7) * 4;
            pa[u] = *(const float4*)&g_all[(jb + row) * ND + c4];
            pb[u] = *(const float4*)&g_all[(kb + row) * ND + c4];
        }

        float acc[4][4] = {};
        for (int ch = 0; ch < 8; ch++) {
            __syncthreads();
            #pragma unroll
            for (int u = 0; u < 2; u++) {
                int idx = t + u * 256, row = idx >> 3, c4 = (idx & 7) * 4;
                As[row * 33 + c4 + 0] = pa[u].x; As[row * 33 + c4 + 1] = pa[u].y;
                As[row * 33 + c4 + 2] = pa[u].z; As[row * 33 + c4 + 3] = pa[u].w;
                Bs[row * 33 + c4 + 0] = pb[u].x; Bs[row * 33 + c4 + 1] = pb[u].y;
                Bs[row * 33 + c4 + 2] = pb[u].z; Bs[row * 33 + c4 + 3] = pb[u].w;
            }
            __syncthreads();
            if (ch < 7) {
                int k0 = (ch + 1) * 32;
                #pragma unroll
                for (int u = 0; u < 2; u++) {
                    int idx = t + u * 256, row = idx >> 3, c4 = (idx & 7) * 4;
                    pa[u] = *(const float4*)&g_all[(jb + row) * ND + k0 + c4];
                    pb[u] = *(const float4*)&g_all[(kb + row) * ND + k0 + c4];
                }
            }
            #pragma unroll
            for (int dd = 0; dd < 32; dd++) {
                float a0 = As[(ty*4+0)*33 + dd], a1 = As[(ty*4+1)*33 + dd],
                      a2 = As[(ty*4+2)*33 + dd], a3 = As[(ty*4+3)*33 + dd];
                float b0 = Bs[(tx*4+0)*33 + dd], b1 = Bs[(tx*4+1)*33 + dd],
                      b2 = Bs[(tx*4+2)*33 + dd], b3 = Bs[(tx*4+3)*33 + dd];
                acc[0][0] = fmaf(a0,b0,acc[0][0]); acc[0][1] = fmaf(a0,b1,acc[0][1]);
                acc[0][2] = fmaf(a0,b2,acc[0][2]); acc[0][3] = fmaf(a0,b3,acc[0][3]);
                acc[1][0] = fmaf(a1,b0,acc[1][0]); acc[1][1] = fmaf(a1,b1,acc[1][1]);
                acc[1][2] = fmaf(a1,b2,acc[1][2]); acc[1][3] = fmaf(a1,b3,acc[1][3]);
                acc[2][0] = fmaf(a2,b0,acc[2][0]); acc[2][1] = fmaf(a2,b1,acc[2][1]);
                acc[2][2] = fmaf(a2,b2,acc[2][2]); acc[2][3] = fmaf(a2,b3,acc[2][3]);
                acc[3][0] = fmaf(a3,b0,acc[3][0]); acc[3][1] = fmaf(a3,b1,acc[3][1]);
                acc[3][2] = fmaf(a3,b2,acc[3][2]); acc[3][3] = fmaf(a3,b3,acc[3][3]);
            }
        }

        float er[4][4];
        #pragma unroll
        for (int i = 0; i < 4; i++) {
            er[i][0] = expf(acc[i][0]); er[i][1] = expf(acc[i][1]);
            er[i][2] = expf(acc[i][2]); er[i][3] = expf(acc[i][3]);
            float4 r = make_float4(er[i][0], er[i][1], er[i][2], er[i][3]);
            *(float4*)&g_E[(jb + ty * 4 + i) * NM + kb + tx * 4] = r;
        }

        if (jt < 12) {
            if (jt != kt) {               // mirror write via smem transpose
                __syncthreads();
                float* Tr = sbuf;         // 64*65 = 4160 <= 4224 floats
                #pragma unroll
                for (int i = 0; i < 4; i++)
                    #pragma unroll
                    for (int l = 0; l < 4; l++)
                        Tr[(tx * 4 + l) * 65 + ty * 4 + i] = er[i][l];
                __syncthreads();
                #pragma unroll
                for (int u = 0; u < 4; u++) {
                    int idx = t + u * 256;
                    int r = idx >> 4, c4 = (idx & 15) * 4;
                    float4 v = make_float4(Tr[r*65 + c4], Tr[r*65 + c4 + 1],
                                           Tr[r*65 + c4 + 2], Tr[r*65 + c4 + 3]);
                    *(float4*)&g_E[(kb + r) * NM + jb + c4] = v;
                }
            }
        } else {
            // anchor-row tile: masked Ea row sums (fixed-point, order-free)
            #pragma unroll
            for (int i = 0; i < 4; i++) {
                int b = ty * 4 + i;       // anchor index (48..63 = pad)
                float part = 0.f;
                if (b < NB) {
                    int mb = lab[b];
                    #pragma unroll
                    for (int l = 0; l < 4; l++) {
                        int col = kb + tx * 4 + l;
                        if (lab[col >> 4] != mb) part += er[i][l];
                    }
                }
                #pragma unroll
                for (int o = 8; o > 0; o >>= 1)
                    part += __shfl_down_sync(0xffffffffu, part, o, 16);
                if (tx == 0 && b < NB)
                    atomicAdd(&g_csum[b],
                              (unsigned long long)(long long)llrintf(part * SCALE_C));
            }
        }
    }

    grid_sync(2 * NBLK);

    // ---------------- phase 2: warp-per-pair symmetric KL (cancellation-free)
    // e=c*Et, a=c*Ea, t=e-a, mu=exp(e)-1 (series), d=mu-nu=t*h (series)
    // symKL = 0.5*(Sdt*D1 - Sd*N1)/(D1*D2); D1=n+Smu, N1=St+Smut, D2=D1-Sd
    int np = (int)g_pcnt;
    for (int p = bid * 8 + w; p < np; p += NBLK * 8) {
        int pr = g_pairs[p];
        int b = pr >> 16, j = pr & 0xffff;
        int mb = lab[b];
        float c = SCALE_C / (float)(long long)g_csum[b];
        const float* Et = g_E + j * NM;
        const float* Ea = g_E + (NM + b) * NM;

        float s0 = 0.f, s1 = 0.f, s2 = 0.f, s3 = 0.f, s4 = 0.f;
        #pragma unroll 4
        for (int i = 0; i < NM / 32; i++) {
            int k = i * 32 + lane;
            float m  = (lab[k >> 4] != mb) ? c : 0.f;   // zeroed lanes give 0 terms
            float e  = m * Et[k];
            float a  = m * Ea[k];
            float tt = e - a;
            float mu = e * (1.f + e * (0.5f + e * (1.f/6.f + e * (1.f/24.f))));
            float sp = e + a;
            float e2 = e * e, ea = e * a, a2 = a * a;
            float h  = 1.f + 0.5f * sp + (e2 + ea + a2) * (1.f/6.f)
                     + sp * (e2 + a2) * (1.f/24.f);
            float d  = tt * h;
            s0 += tt; s1 += mu; s2 = fmaf(mu, tt, s2);
            s3 += d;  s4 = fmaf(tt, d, s4);
        }
        #pragma unroll
        for (int o = 16; o > 0; o >>= 1) {
            s0 += __shfl_down_sync(0xffffffffu, s0, o);
            s1 += __shfl_down_sync(0xffffffffu, s1, o);
            s2 += __shfl_down_sync(0xffffffffu, s2, o);
            s3 += __shfl_down_sync(0xffffffffu, s3, o);
            s4 += __shfl_down_sync(0xffffffffu, s4, o);
        }
        if (lane == 0) {
            float n  = g_nneg[b];
            float D1 = n + s1;
            float N1 = s0 + s2;
            float D2 = D1 - s3;
            float kl = 0.5f * (s4 * D1 - s3 * N1) / (D1 * D2);
            atomicAdd(&g_rowsum[b],
                      (unsigned long long)(long long)llrintf(kl * SCALE_KL));
        }
    }

    // ---------------- final: last block emits scalar + resets state for replay
    __threadfence();
    __syncthreads();
    if (t == 0) ticket_s = atomicAdd(&g_done, 1u);
    __syncthreads();
    if (ticket_s == NBLK - 1 && t == 0) {
        float tot = 0.f;
        for (int b = 0; b < NB; b++) {
            float rs = (float)(long long)g_rowsum[b] * (1.f / SCALE_KL);
            tot += rs / g_P[b];
            g_rowsum[b] = 0ull;
            g_csum[b]   = 0ull;
        }
        out[0] = tot / (float)NB;
        g_pcnt = 0u;
        g_done = 0u;
        g_bar  = 0u;
    }
}

// ----------------------------------------------------------------- launch
extern "C" void kernel_launch(void* const* d_in, const int* in_sizes, int n_in,
                              void* d_out, int out_size) {
    const float* x     = (const float*)d_in[0];
    const int*   lab32 = (const int*)  d_in[1];
    float*       out   = (float*)      d_out;
    (void)in_sizes; (void)n_in; (void)out_size;

    k_fused<<<NBLK, 256>>>(x, lab32, out);
}

// round 10
// speedup vs baseline: 1.0641x; 1.0641x over previous
#include <cuda_runtime.h>

#define NB 48
#define NL 17
#define ND 256
#define NM 768    /* NB*(L-1) */
#define NR 832    /* NM + NB anchors = 13*64 */
#define PAIR_BLOCKS 768
#define NTILES 90 /* 78 upper-tri tok tiles + 12 anchor-row tiles */
#define NPB 144   /* pair-build blocks: 48*768/256 */

#define SCALE_C  4294967296.0f           /* 2^32 for csum fixed-point */
#define SCALE_KL 1.125899906842624e15f   /* 2^50 for kl fixed-point */

__device__ float g_all [NR*ND];   // rows 0..767 toks, 768..815 anchors, 816..831 zero
__device__ float g_E   [NR*NM];   // exp(sims): rows 0..767 Et (symmetric), 768..815 Ea
__device__ float g_nneg[NB];
__device__ float g_P   [NB];
__device__ int   g_lab [NB];
__device__ int   g_pairs[NB*NM];  // (b<<16)|j, unordered (consumers are order-free)
__device__ unsigned int       g_pcnt;        // zero-init; reset by k_pairs final block
__device__ unsigned long long g_csum  [NB];  // sum_neg Ea[b,k] * 2^32
__device__ unsigned long long g_rowsum[NB];  // sum_j kl[b,j]   * 2^50
__device__ unsigned int       g_done;

// ---------------------------------------------------------------- utilities
__device__ __forceinline__ float blockReduceSum(float v, volatile float* sm) {
    int lane = threadIdx.x & 31, wid = threadIdx.x >> 5;
    #pragma unroll
    for (int o = 16; o > 0; o >>= 1) v += __shfl_down_sync(0xffffffffu, v, o);
    if (lane == 0) sm[wid] = v;
    __syncthreads();
    if (threadIdx.x < 32) {
        float r = (threadIdx.x < 8) ? sm[threadIdx.x] : 0.f;
        #pragma unroll
        for (int o = 4; o > 0; o >>= 1) r += __shfl_down_sync(0xffffffffu, r, o);
        if (threadIdx.x == 0) sm[0] = r;
    }
    __syncthreads();
    float r = sm[0];
    __syncthreads();
    return r;
}

// Reference declares int64 labels; jax w/o x64 silently yields int32. An
// int64 buffer (values 0..7, little-endian) read as int32 is [v,0,v,0,...].
__device__ __forceinline__ void load_labels(const int* __restrict__ lab32,
                                            int* lab, int* flag) {
    int t = threadIdx.x;
    if (t == 0) {
        bool is64 = true;
        for (int i = 1; i < NB; i += 2) if (lab32[i] != 0) { is64 = false; break; }
        if (is64) for (int i = 0; i < NB; i += 2) {
            int v = lab32[i];
            if (v < 0 || v >= 8) { is64 = false; break; }
        }
        *flag = is64 ? 1 : 0;
    }
    __syncthreads();
    if (t < NB) lab[t] = (*flag) ? (int)((const long long*)lab32)[t] : lab32[t];
    __syncthreads();
}

// ---- 0: fully parallel prep.
// blocks 0..831: normalize/pad rows. blocks 832..975: build pair list.
// block 976: per-b scalars.
__global__ void k_prep(const float* __restrict__ x, const int* __restrict__ lab32) {
    int bid = blockIdx.x, t = threadIdx.x;
    if (bid < NR) {                       // normalize rows / zero pad
        __shared__ float red[32];
        int r = bid, d = t;
        if (r >= NB * NL) {
            g_all[(NM + r - NB * NL + NB) * ND + d] = 0.f;
            return;
        }
        float v = x[r * ND + d];
        float ss = blockReduceSum(v * v, red);
        float inv = 1.f / fmaxf(sqrtf(ss), 1e-12f);
        float xn = v * inv;
        int b = r / NL, p = r - b * NL;
        int row = (p == 0) ? (NM + b) : (b * (NL - 1) + p - 1);
        g_all[row * ND + d] = xn;
        return;
    }
    __shared__ int lab[NB];
    __shared__ int flag;
    load_labels(lab32, lab, &flag);
    if (bid < NR + NPB) {                 // pair list (unordered, atomic append)
        int p = (bid - NR) * 256 + t;     // 0..36863
        int b = p / NM, j = p - b * NM;
        if (lab[j >> 4] == lab[b]) {
            unsigned pos = atomicAdd(&g_pcnt, 1u);
            g_pairs[pos] = (b << 16) | j;
        }
        return;
    }
    // scalars
    if (t < NB) {
        int same = 0;
        #pragma unroll 8
        for (int o = 0; o < NB; o++) same += (lab[o] == lab[t]) ? 1 : 0;
        g_lab[t]  = lab[t];
        g_nneg[t] = (float)((NB - same) * (NL - 1));
        g_P[t]    = (float)(same * (NL - 1));
    }
}

// B-tile swizzled smem index: value (col c, row r) lives at 16B-unit
// c*16 + ((r>>2) ^ (c&15)), byte offset unit*16 + (r&3)*4. A dd-column read
// for rowgroup g is then ONE aligned float4 at unit dd*16 + (g ^ (dd&15)).
__device__ __forceinline__ int bswz(int c, int r) {
    return ((c * 16 + ((r >> 2) ^ (c & 15))) << 2) + (r & 3);
}

// --------- 1: symmetric GEMM, exp epilogue, mirror write for off-diag tiles,
//              fused csum accumulation on anchor-row tiles (jt==12)
// tiles: id 0..77 -> (jt,kt) upper triangle of 12x12 tok grid; 78..89 -> (12,kt)
__global__ void k_gemm(void) {
    __shared__ float sbuf[4160];      // As 64x33 (2112) + BsT 2048; reused as Tr 64x65
    __shared__ int lab[NB];
    float* As  = sbuf;
    float* BsT = sbuf + 2112;
    int t = threadIdx.x, tx = t & 15, ty = t >> 4;
    if (t < NB) lab[t] = g_lab[t];

    int id = blockIdx.x, jt, kt;
    if (id < 78) {
        jt = 0; int rem = id;
        while (rem >= 12 - jt) { rem -= 12 - jt; jt++; }
        kt = jt + rem;
    } else { jt = 12; kt = id - 78; }
    int jb = jt * 64, kb = kt * 64;

    // register prefetch of chunk 0
    float4 pa[2], pb[2];
    #pragma unroll
    for (int u = 0; u < 2; u++) {
        int idx = t + u * 256, row = idx >> 3, c4 = (idx & 7) * 4;
        pa[u] = *(const float4*)&g_all[(jb + row) * ND + c4];
        pb[u] = *(const float4*)&g_all[(kb + row) * ND + c4];
    }

    float acc[4][4] = {};
    for (int ch = 0; ch < 8; ch++) {
        __syncthreads();
        #pragma unroll
        for (int u = 0; u < 2; u++) {
            int idx = t + u * 256, row = idx >> 3, c4 = (idx & 7) * 4;
            As[row * 33 + c4 + 0] = pa[u].x; As[row * 33 + c4 + 1] = pa[u].y;
            As[row * 33 + c4 + 2] = pa[u].z; As[row * 33 + c4 + 3] = pa[u].w;
            BsT[bswz(c4 + 0, row)] = pb[u].x;
            BsT[bswz(c4 + 1, row)] = pb[u].y;
            BsT[bswz(c4 + 2, row)] = pb[u].z;
            BsT[bswz(c4 + 3, row)] = pb[u].w;
        }
        __syncthreads();
        if (ch < 7) {
            int k0 = (ch + 1) * 32;
            #pragma unroll
            for (int u = 0; u < 2; u++) {
                int idx = t + u * 256, row = idx >> 3, c4 = (idx & 7) * 4;
                pa[u] = *(const float4*)&g_all[(jb + row) * ND + k0 + c4];
                pb[u] = *(const float4*)&g_all[(kb + row) * ND + k0 + c4];
            }
        }
        // inner loop with dd+1 register prefetch (LDS->use distance = 16 FFMA)
        float a0 = As[(ty*4+0)*33], a1 = As[(ty*4+1)*33],
              a2 = As[(ty*4+2)*33], a3 = As[(ty*4+3)*33];
        float4 bv = *(const float4*)&BsT[(0 * 16 + (tx ^ 0)) << 2];
        #pragma unroll
        for (int dd = 0; dd < 32; dd++) {
            float na0, na1, na2, na3; float4 nbv;
            if (dd < 31) {
                int d1 = dd + 1;
                na0 = As[(ty*4+0)*33 + d1]; na1 = As[(ty*4+1)*33 + d1];
                na2 = As[(ty*4+2)*33 + d1]; na3 = As[(ty*4+3)*33 + d1];
                nbv = *(const float4*)&BsT[((d1 << 4) + (tx ^ (d1 & 15))) << 2];
            }
            acc[0][0] = fmaf(a0,bv.x,acc[0][0]); acc[0][1] = fmaf(a0,bv.y,acc[0][1]);
            acc[0][2] = fmaf(a0,bv.z,acc[0][2]); acc[0][3] = fmaf(a0,bv.w,acc[0][3]);
            acc[1][0] = fmaf(a1,bv.x,acc[1][0]); acc[1][1] = fmaf(a1,bv.y,acc[1][1]);
            acc[1][2] = fmaf(a1,bv.z,acc[1][2]); acc[1][3] = fmaf(a1,bv.w,acc[1][3]);
            acc[2][0] = fmaf(a2,bv.x,acc[2][0]); acc[2][1] = fmaf(a2,bv.y,acc[2][1]);
            acc[2][2] = fmaf(a2,bv.z,acc[2][2]); acc[2][3] = fmaf(a2,bv.w,acc[2][3]);
            acc[3][0] = fmaf(a3,bv.x,acc[3][0]); acc[3][1] = fmaf(a3,bv.y,acc[3][1]);
            acc[3][2] = fmaf(a3,bv.z,acc[3][2]); acc[3][3] = fmaf(a3,bv.w,acc[3][3]);
            if (dd < 31) { a0 = na0; a1 = na1; a2 = na2; a3 = na3; bv = nbv; }
        }
    }

    // exp + direct coalesced write
    float er[4][4];
    #pragma unroll
    for (int i = 0; i < 4; i++) {
        er[i][0] = expf(acc[i][0]); er[i][1] = expf(acc[i][1]);
        er[i][2] = expf(acc[i][2]); er[i][3] = expf(acc[i][3]);
        float4 r = make_float4(er[i][0], er[i][1], er[i][2], er[i][3]);
        *(float4*)&g_E[(jb + ty * 4 + i) * NM + kb + tx * 4] = r;
    }

    if (jt < 12) {
        if (jt != kt) {
            // mirror write via smem transpose (stride 65)
            __syncthreads();                 // done with As/BsT
            float* Tr = sbuf;                // 64*65 = 4160 floats, exact fit
            #pragma unroll
            for (int i = 0; i < 4; i++)
                #pragma unroll
                for (int l = 0; l < 4; l++)
                    Tr[(tx * 4 + l) * 65 + ty * 4 + i] = er[i][l];
            __syncthreads();
            #pragma unroll
            for (int u = 0; u < 4; u++) {
                int idx = t + u * 256;       // 1024 float4 = 64 rows x 16
                int r = idx >> 4, c4 = (idx & 15) * 4;
                float4 v = make_float4(Tr[r*65 + c4], Tr[r*65 + c4 + 1],
                                       Tr[r*65 + c4 + 2], Tr[r*65 + c4 + 3]);
                *(float4*)&g_E[(kb + r) * NM + jb + c4] = v;
            }
        }
    } else {
        // anchor-row tile: accumulate masked Ea row sums (fixed-point, order-free)
        #pragma unroll
        for (int i = 0; i < 4; i++) {
            int b = ty * 4 + i;              // anchor index (48..63 = pad)
            float part = 0.f;
            if (b < NB) {
                int mb = lab[b];
                #pragma unroll
                for (int l = 0; l < 4; l++) {
                    int col = kb + tx * 4 + l;
                    if (lab[col >> 4] != mb) part += er[i][l];
                }
            }
            #pragma unroll
            for (int o = 8; o > 0; o >>= 1)
                part += __shfl_down_sync(0xffffffffu, part, o, 16);
            if (tx == 0 && b < NB)
                atomicAdd(&g_csum[b],
                          (unsigned long long)(long long)llrintf(part * SCALE_C));
        }
    }
}

// ------------- 2: warp-per-pair symmetric KL + in-kernel final reduction
// e=c*Et, a=c*Ea, t=e-a, mu=exp(e)-1 (series), d=mu-nu=t*h (series)
// symKL = 0.5*(Sdt*D1 - Sd*N1)/(D1*D2); D1=n+Smu, N1=St+Smut, D2=D1-Sd
// Pair order is irrelevant: per-pair kl is a pure function of globals and the
// accumulation is integer fixed-point -> bit-identical across replays.
__global__ void k_pairs(float* __restrict__ out) {
    __shared__ int lab[NB];
    __shared__ unsigned int ticket_s;
    int t = threadIdx.x, lane = t & 31, w = t >> 5;
    if (t < NB) lab[t] = g_lab[t];
    __syncthreads();
    int np = (int)g_pcnt;
    for (int p = blockIdx.x * 8 + w; p < np; p += PAIR_BLOCKS * 8) {
        int pr = g_pairs[p];
        int b = pr >> 16, j = pr & 0xffff;
        int mb = lab[b];
        float c = SCALE_C / (float)(long long)g_csum[b];
        const float* Et = g_E + j * NM;
        const float* Ea = g_E + (NM + b) * NM;

        float s0 = 0.f, s1 = 0.f, s2 = 0.f, s3 = 0.f, s4 = 0.f;
        #pragma unroll 4
        for (int i = 0; i < NM / 32; i++) {
            int k = i * 32 + lane;
            float m  = (lab[k >> 4] != mb) ? c : 0.f;   // zeroed lanes give 0 terms
            float e  = m * Et[k];
            float a  = m * Ea[k];
            float tt = e - a;
            float mu = e * (1.f + e * (0.5f + e * (1.f/6.f + e * (1.f/24.f))));
            float sp = e + a;
            float e2 = e * e, ea = e * a, a2 = a * a;
            float h  = 1.f + 0.5f * sp + (e2 + ea + a2) * (1.f/6.f)
                     + sp * (e2 + a2) * (1.f/24.f);
            float d  = tt * h;
            s0 += tt; s1 += mu; s2 = fmaf(mu, tt, s2);
            s3 += d;  s4 = fmaf(tt, d, s4);
        }
        #pragma unroll
        for (int o = 16; o > 0; o >>= 1) {
            s0 += __shfl_down_sync(0xffffffffu, s0, o);
            s1 += __shfl_down_sync(0xffffffffu, s1, o);
            s2 += __shfl_down_sync(0xffffffffu, s2, o);
            s3 += __shfl_down_sync(0xffffffffu, s3, o);
            s4 += __shfl_down_sync(0xffffffffu, s4, o);
        }
        if (lane == 0) {
            float n  = g_nneg[b];
            float D1 = n + s1;
            float N1 = s0 + s2;
            float D2 = D1 - s3;
            float kl = 0.5f * (s4 * D1 - s3 * N1) / (D1 * D2);
            atomicAdd(&g_rowsum[b],
                      (unsigned long long)(long long)llrintf(kl * SCALE_KL));
        }
    }
    // last block: final scalar + reset all counters for the next graph replay
    __threadfence();
    __syncthreads();
    if (t == 0) ticket_s = atomicAdd(&g_done, 1u);
    __syncthreads();
    if (ticket_s == PAIR_BLOCKS - 1 && t == 0) {
        float tot = 0.f;
        for (int b = 0; b < NB; b++) {
            float rs = (float)(long long)g_rowsum[b] * (1.f / SCALE_KL);
            tot += rs / g_P[b];
            g_rowsum[b] = 0ull;
            g_csum[b]   = 0ull;
        }
        out[0] = tot / (float)NB;
        g_pcnt = 0u;
        g_done = 0u;
    }
}

// ----------------------------------------------------------------- launch
extern "C" void kernel_launch(void* const* d_in, const int* in_sizes, int n_in,
                              void* d_out, int out_size) {
    const float* x     = (const float*)d_in[0];
    const int*   lab32 = (const int*)  d_in[1];
    float*       out   = (float*)      d_out;
    (void)in_sizes; (void)n_in; (void)out_size;

    k_prep <<<NR + NPB + 1, 256>>>(x, lab32);
    k_gemm <<<NTILES, 256>>>();
    k_pairs<<<PAIR_BLOCKS, 256>>>(out);
}

// round 12
// speedup vs baseline: 1.2490x; 1.1738x over previous
#include <cuda_runtime.h>
#include <cstdint>

#define NB 48
#define NL 17
#define ND 256
#define NM 768    /* NB*(L-1) */
#define NR 832    /* NM + NB anchors = 13*64 */
#define PAIR_BLOCKS 768
#define NTILES 90 /* 78 upper-tri tok tiles + 12 anchor-row tiles */
#define PREP_BLOCKS 249

#define SCALE_C  4294967296.0f           /* 2^32 for csum fixed-point */
#define SCALE_KL 1.125899906842624e15f   /* 2^50 for kl fixed-point */

__device__ float g_hi  [NR*ND];   // tf32-rounded normalized rows
__device__ float g_lo  [NR*ND];   // tf32 residual
__device__ float g_E   [NR*NM];   // exp(sims): rows 0..767 Et, 768..815 Ea
__device__ float g_nneg[NB];
__device__ float g_P   [NB];
__device__ int   g_lab [NB];
__device__ int   g_pairs[NB*NM];  // (b<<16)|j, unordered (consumers order-free)
__device__ unsigned int       g_pcnt;        // zero-init; reset by k_pairs final block
__device__ unsigned long long g_csum  [NB];  // sum_neg Ea[b,k] * 2^32
__device__ unsigned long long g_rowsum[NB];  // sum_j kl[b,j]   * 2^50
__device__ unsigned int       g_done;

// ---------------------------------------------------------------- utilities
__device__ __forceinline__ float tf32r(float x) {
    float h;
    asm("cvt.rna.tf32.f32 %0, %1;" : "=f"(h) : "f"(x));
    return h;
}
__device__ __forceinline__ void mma_tf32(float& d0, float& d1, float& d2, float& d3,
                                         uint32_t a0, uint32_t a1, uint32_t a2,
                                         uint32_t a3, uint32_t b0, uint32_t b1) {
    asm volatile(
        "mma.sync.aligned.m16n8k8.row.col.f32.tf32.tf32.f32 "
        "{%0,%1,%2,%3}, {%4,%5,%6,%7}, {%8,%9}, {%0,%1,%2,%3};"
        : "+f"(d0), "+f"(d1), "+f"(d2), "+f"(d3)
        : "r"(a0), "r"(a1), "r"(a2), "r"(a3), "r"(b0), "r"(b1));
}

// Reference declares int64 labels; jax w/o x64 silently yields int32. An
// int64 buffer (values 0..7, little-endian) read as int32 is [v,0,v,0,...].
__device__ __forceinline__ void load_labels(const int* __restrict__ lab32,
                                            int* lab, int* flag) {
    int t = threadIdx.x;
    if (t == 0) {
        bool is64 = true;
        for (int i = 1; i < NB; i += 2) if (lab32[i] != 0) { is64 = false; break; }
        if (is64) for (int i = 0; i < NB; i += 2) {
            int v = lab32[i];
            if (v < 0 || v >= 8) { is64 = false; break; }
        }
        *flag = is64 ? 1 : 0;
    }
    __syncthreads();
    if (t < NB) lab[t] = (*flag) ? (int)((const long long*)lab32)[t] : lab32[t];
    __syncthreads();
}

// ---- 0: prep. blocks 0..101: warp-per-row norm + tf32 hi/lo split (816 rows);
// 102..103: zero pads (rows 816..831); 104..247: pair list; 248: scalars.
__global__ void k_prep(const float* __restrict__ x, const int* __restrict__ lab32) {
    int bid = blockIdx.x, t = threadIdx.x, w = t >> 5, lane = t & 31;
    if (bid < 102) {
        int r = bid * 8 + w;             // 0..815
        const float4* src = (const float4*)&x[r * ND];
        float4 v0 = src[lane], v1 = src[lane + 32];
        float ss = v0.x*v0.x + v0.y*v0.y + v0.z*v0.z + v0.w*v0.w
                 + v1.x*v1.x + v1.y*v1.y + v1.z*v1.z + v1.w*v1.w;
        #pragma unroll
        for (int o = 16; o > 0; o >>= 1) ss += __shfl_xor_sync(0xffffffffu, ss, o);
        float inv = 1.f / fmaxf(sqrtf(ss), 1e-12f);
        int b = r / NL, p = r - b * NL;
        int row = (p == 0) ? (NM + b) : (b * (NL - 1) + p - 1);
        float4* dh = (float4*)&g_hi[row * ND];
        float4* dl = (float4*)&g_lo[row * ND];
        float4 n0 = make_float4(v0.x*inv, v0.y*inv, v0.z*inv, v0.w*inv);
        float4 n1 = make_float4(v1.x*inv, v1.y*inv, v1.z*inv, v1.w*inv);
        float4 h0 = make_float4(tf32r(n0.x), tf32r(n0.y), tf32r(n0.z), tf32r(n0.w));
        float4 h1 = make_float4(tf32r(n1.x), tf32r(n1.y), tf32r(n1.z), tf32r(n1.w));
        dh[lane]      = h0;
        dh[lane + 32] = h1;
        dl[lane]      = make_float4(tf32r(n0.x - h0.x), tf32r(n0.y - h0.y),
                                    tf32r(n0.z - h0.z), tf32r(n0.w - h0.w));
        dl[lane + 32] = make_float4(tf32r(n1.x - h1.x), tf32r(n1.y - h1.y),
                                    tf32r(n1.z - h1.z), tf32r(n1.w - h1.w));
        return;
    }
    if (bid < 104) {                     // zero pad rows 816..831
        int r = 816 + (bid - 102) * 8 + w;
        float4 z = make_float4(0.f, 0.f, 0.f, 0.f);
        float4* dh = (float4*)&g_hi[r * ND];
        float4* dl = (float4*)&g_lo[r * ND];
        dh[lane] = z; dh[lane + 32] = z;
        dl[lane] = z; dl[lane + 32] = z;
        return;
    }
    __shared__ int lab[NB];
    __shared__ int flag;
    load_labels(lab32, lab, &flag);
    if (bid < 248) {                     // pair list (unordered atomic append)
        int p = (bid - 104) * 256 + t;   // 0..36863
        int b = p / NM, j = p - b * NM;
        if (lab[j >> 4] == lab[b]) {
            unsigned pos = atomicAdd(&g_pcnt, 1u);
            g_pairs[pos] = (b << 16) | j;
        }
        return;
    }
    if (t < NB) {
        int same = 0;
        #pragma unroll 8
        for (int o = 0; o < NB; o++) same += (lab[o] == lab[t]) ? 1 : 0;
        g_lab[t]  = lab[t];
        g_nneg[t] = (float)((NB - same) * (NL - 1));
        g_P[t]    = (float)(same * (NL - 1));
    }
}

// ---- 1: symmetric GEMM via mma.sync tf32x3, exp epilogue, mirror write for
// off-diag tok tiles, fused csum on anchor-row tiles (jt==12).
// tiles: id 0..77 -> (jt,kt) upper triangle of 12x12 tok grid; 78..89 -> (12,kt)
// smem tiles stride 36 floats: fragment banks = (4n + k) mod 32, conflict-free.
__global__ void __launch_bounds__(256) k_gemm(void) {
    __shared__ __align__(16) float sbuf[4 * 64 * 36];   // Ah, Al, Bh, Bl (36.9KB)
    __shared__ int lab[NB];
    float* sAh = sbuf;
    float* sAl = sbuf + 2304;
    float* sBh = sbuf + 4608;
    float* sBl = sbuf + 6912;
    int t = threadIdx.x, w = t >> 5, lane = t & 31;
    int wr = (w & 3) * 16, wn = (w >> 2) * 32;          // warp tile: rows 16, cols 32
    if (t < NB) lab[t] = g_lab[t];

    int id = blockIdx.x, jt, kt;
    if (id < 78) {
        jt = 0; int rem = id;
        while (rem >= 12 - jt) { rem -= 12 - jt; jt++; }
        kt = jt + rem;
    } else { jt = 12; kt = id - 78; }
    int jb = jt * 64, kb = kt * 64;

    // prefetch chunk 0 (Kc = 32): 2 float4 per thread per buffer
    float4 pf[8];
    #pragma unroll
    for (int u = 0; u < 2; u++) {
        int idx = t + u * 256, row = idx >> 3, c4 = (idx & 7) * 4;
        pf[u * 4 + 0] = *(const float4*)&g_hi[(jb + row) * ND + c4];
        pf[u * 4 + 1] = *(const float4*)&g_lo[(jb + row) * ND + c4];
        pf[u * 4 + 2] = *(const float4*)&g_hi[(kb + row) * ND + c4];
        pf[u * 4 + 3] = *(const float4*)&g_lo[(kb + row) * ND + c4];
    }

    float acc[4][4] = {};                // 4 n-blocks x 4 regs (m16n8 frags)
    int ar0 = (wr + (lane >> 2)) * 36 + (lane & 3);
    for (int ch = 0; ch < 8; ch++) {
        __syncthreads();
        #pragma unroll
        for (int u = 0; u < 2; u++) {
            int idx = t + u * 256, row = idx >> 3, c4 = (idx & 7) * 4;
            *(float4*)&sAh[row * 36 + c4] = pf[u * 4 + 0];
            *(float4*)&sAl[row * 36 + c4] = pf[u * 4 + 1];
            *(float4*)&sBh[row * 36 + c4] = pf[u * 4 + 2];
            *(float4*)&sBl[row * 36 + c4] = pf[u * 4 + 3];
        }
        __syncthreads();
        if (ch < 7) {
            int k0g = (ch + 1) * 32;
            #pragma unroll
            for (int u = 0; u < 2; u++) {
                int idx = t + u * 256, row = idx >> 3, c4 = (idx & 7) * 4;
                pf[u * 4 + 0] = *(const float4*)&g_hi[(jb + row) * ND + k0g + c4];
                pf[u * 4 + 1] = *(const float4*)&g_lo[(jb + row) * ND + k0g + c4];
                pf[u * 4 + 2] = *(const float4*)&g_hi[(kb + row) * ND + k0g + c4];
                pf[u * 4 + 3] = *(const float4*)&g_lo[(kb + row) * ND + k0g + c4];
            }
        }
        #pragma unroll
        for (int ks = 0; ks < 4; ks++) {
            int k0 = ks * 8;
            uint32_t ah0 = __float_as_uint(sAh[ar0 + k0]);
            uint32_t ah1 = __float_as_uint(sAh[ar0 + 8 * 36 + k0]);
            uint32_t ah2 = __float_as_uint(sAh[ar0 + k0 + 4]);
            uint32_t ah3 = __float_as_uint(sAh[ar0 + 8 * 36 + k0 + 4]);
            uint32_t al0 = __float_as_uint(sAl[ar0 + k0]);
            uint32_t al1 = __float_as_uint(sAl[ar0 + 8 * 36 + k0]);
            uint32_t al2 = __float_as_uint(sAl[ar0 + k0 + 4]);
            uint32_t al3 = __float_as_uint(sAl[ar0 + 8 * 36 + k0 + 4]);
            #pragma unroll
            for (int nb = 0; nb < 4; nb++) {
                int br = (wn + nb * 8 + (lane >> 2)) * 36 + k0 + (lane & 3);
                uint32_t bh0 = __float_as_uint(sBh[br]);
                uint32_t bh1 = __float_as_uint(sBh[br + 4]);
                uint32_t bl0 = __float_as_uint(sBl[br]);
                uint32_t bl1 = __float_as_uint(sBl[br + 4]);
                mma_tf32(acc[nb][0], acc[nb][1], acc[nb][2], acc[nb][3],
                         ah0, ah1, ah2, ah3, bh0, bh1);
                mma_tf32(acc[nb][0], acc[nb][1], acc[nb][2], acc[nb][3],
                         ah0, ah1, ah2, ah3, bl0, bl1);
                mma_tf32(acc[nb][0], acc[nb][1], acc[nb][2], acc[nb][3],
                         al0, al1, al2, al3, bh0, bh1);
            }
        }
    }

    // stage exp(result) in Tr[64][65] (aliases sbuf: 4160 <= 9216 floats)
    __syncthreads();
    float* Tr = sbuf;
    {
        int r0 = wr + (lane >> 2), c0 = wn + 2 * (lane & 3);
        #pragma unroll
        for (int nb = 0; nb < 4; nb++) {
            int cc = c0 + nb * 8;
            Tr[r0 * 65 + cc]           = __expf(acc[nb][0]);
            Tr[r0 * 65 + cc + 1]       = __expf(acc[nb][1]);
            Tr[(r0 + 8) * 65 + cc]     = __expf(acc[nb][2]);
            Tr[(r0 + 8) * 65 + cc + 1] = __expf(acc[nb][3]);
        }
    }
    __syncthreads();

    // coalesced E write
    #pragma unroll
    for (int u = 0; u < 4; u++) {
        int idx = t + u * 256;           // 1024 float4 = 64 rows x 16
        int r = idx >> 4, c4 = (idx & 15) * 4;
        float4 v = make_float4(Tr[r*65 + c4], Tr[r*65 + c4 + 1],
                               Tr[r*65 + c4 + 2], Tr[r*65 + c4 + 3]);
        *(float4*)&g_E[(jb + r) * NM + kb + c4] = v;
    }
    if (jt < 12) {
        if (jt != kt) {                  // transpose mirror
            #pragma unroll
            for (int u = 0; u < 4; u++) {
                int idx = t + u * 256;
                int r = idx >> 4, c4 = (idx & 15) * 4;
                float4 v = make_float4(Tr[(c4+0)*65 + r], Tr[(c4+1)*65 + r],
                                       Tr[(c4+2)*65 + r], Tr[(c4+3)*65 + r]);
                *(float4*)&g_E[(kb + r) * NM + jb + c4] = v;
            }
        }
    } else if (t < NB) {                 // anchor-row tile: csum (fixed-point)
        int mb = lab[t];
        float part = 0.f;
        #pragma unroll 8
        for (int cc = 0; cc < 64; cc++)
            if (lab[(kb + cc) >> 4] != mb) part += Tr[t * 65 + cc];
        atomicAdd(&g_csum[t], (unsigned long long)(long long)llrintf(part * SCALE_C));
    }
}

// ---- 2: warp-per-pair symmetric KL (cancellation-free) + in-kernel finish
// e=c*Et, a=c*Ea, t=e-a, mu=exp(e)-1 (series), d=mu-nu=t*h (series)
// symKL = 0.5*(Sdt*D1 - Sd*N1)/(D1*D2); D1=n+Smu, N1=St+Smut, D2=D1-Sd
// Pair order is irrelevant: per-pair kl is a pure function of globals and the
// accumulation is integer fixed-point -> bit-identical across replays.
__global__ void k_pairs(float* __restrict__ out) {
    __shared__ int lab[NB];
    __shared__ unsigned int ticket_s;
    int t = threadIdx.x, lane = t & 31, w = t >> 5;
    if (t < NB) lab[t] = g_lab[t];
    __syncthreads();
    int np = (int)g_pcnt;
    for (int p = blockIdx.x * 8 + w; p < np; p += PAIR_BLOCKS * 8) {
        int pr = g_pairs[p];
        int b = pr >> 16, j = pr & 0xffff;
        int mb = lab[b];
        float c = SCALE_C / (float)(long long)g_csum[b];
        const float* Et = g_E + j * NM;
        const float* Ea = g_E + (NM + b) * NM;

        float s0 = 0.f, s1 = 0.f, s2 = 0.f, s3 = 0.f, s4 = 0.f;
        #pragma unroll
        for (int i = 0; i < 6; i++) {    // float4 per lane; 4 k share one mask
            int k4 = i * 128 + lane * 4;
            float m = (lab[k4 >> 4] != mb) ? c : 0.f;
            float4 E4 = *(const float4*)&Et[k4];
            float4 A4 = *(const float4*)&Ea[k4];
            #pragma unroll
            for (int u = 0; u < 4; u++) {
                float Ev = (u == 0) ? E4.x : (u == 1) ? E4.y : (u == 2) ? E4.z : E4.w;
                float Av = (u == 0) ? A4.x : (u == 1) ? A4.y : (u == 2) ? A4.z : A4.w;
                float e  = m * Ev;
                float a  = m * Av;
                float tt = e - a;
                float mu = e * (1.f + e * (0.5f + e * (1.f/6.f + e * (1.f/24.f))));
                float sp = e + a;
                float e2 = e * e, ea = e * a, a2 = a * a;
                float h  = 1.f + 0.5f * sp + (e2 + ea + a2) * (1.f/6.f)
                         + sp * (e2 + a2) * (1.f/24.f);
                float d  = tt * h;
                s0 += tt; s1 += mu; s2 = fmaf(mu, tt, s2);
                s3 += d;  s4 = fmaf(tt, d, s4);
            }
        }
        #pragma unroll
        for (int o = 16; o > 0; o >>= 1) {
            s0 += __shfl_down_sync(0xffffffffu, s0, o);
            s1 += __shfl_down_sync(0xffffffffu, s1, o);
            s2 += __shfl_down_sync(0xffffffffu, s2, o);
            s3 += __shfl_down_sync(0xffffffffu, s3, o);
            s4 += __shfl_down_sync(0xffffffffu, s4, o);
        }
        if (lane == 0) {
            float n  = g_nneg[b];
            float D1 = n + s1;
            float N1 = s0 + s2;
            float D2 = D1 - s3;
            float kl = 0.5f * (s4 * D1 - s3 * N1) / (D1 * D2);
            atomicAdd(&g_rowsum[b],
                      (unsigned long long)(long long)llrintf(kl * SCALE_KL));
        }
    }
    // last block: final scalar + reset all counters for the next graph replay
    __threadfence();
    __syncthreads();
    if (t == 0) ticket_s = atomicAdd(&g_done, 1u);
    __syncthreads();
    if (ticket_s == PAIR_BLOCKS - 1 && t == 0) {
        float tot = 0.f;
        for (int b = 0; b < NB; b++) {
            float rs = (float)(long long)g_rowsum[b] * (1.f / SCALE_KL);
            tot += rs / g_P[b];
            g_rowsum[b] = 0ull;
            g_csum[b]   = 0ull;
        }
        out[0] = tot / (float)NB;
        g_pcnt = 0u;
        g_done = 0u;
    }
}

// ----------------------------------------------------------------- launch
extern "C" void kernel_launch(void* const* d_in, const int* in_sizes, int n_in,
                              void* d_out, int out_size) {
    const float* x     = (const float*)d_in[0];
    const int*   lab32 = (const int*)  d_in[1];
    float*       out   = (float*)      d_out;
    (void)in_sizes; (void)n_in; (void)out_size;

    k_prep <<<PREP_BLOCKS, 256>>>(x, lab32);
    k_gemm <<<NTILES, 256>>>();
    k_pairs<<<PAIR_BLOCKS, 256>>>(out);
}

// round 13
// speedup vs baseline: 1.2554x; 1.0051x over previous
#include <cuda_runtime.h>
#include <cstdint>

#define NB 48
#define NL 17
#define ND 256
#define NM 768    /* NB*(L-1) */
#define NR 832    /* NM + NB anchors = 13*64 */
#define PAIR_BLOCKS 768
#define NTILES 90 /* 78 upper-tri tok tiles + 12 anchor-row tiles */
#define PREP_BLOCKS 249

#define SCALE_C  4294967296.0f           /* 2^32 for csum fixed-point */
#define SCALE_KL 1.125899906842624e15f   /* 2^50 for kl fixed-point */

__device__ float g_hi  [NR*ND];   // tf32-rounded normalized rows
__device__ float g_lo  [NR*ND];   // tf32 residual
__device__ float g_E   [NR*NM];   // exp(sims): rows 0..767 Et, 768..815 Ea
__device__ float g_nneg[NB];
__device__ float g_P   [NB];
__device__ int   g_lab [NB];
__device__ int   g_pairs[NB*NM];  // (b<<16)|j, unordered (consumers order-free)
__device__ unsigned int       g_pcnt;        // zero-init; reset by k_pairs final block
__device__ unsigned long long g_csum  [NB];  // sum_neg Ea[b,k] * 2^32
__device__ unsigned long long g_rowsum[NB];  // sum_j kl[b,j]   * 2^50
__device__ unsigned int       g_done;

// ---------------------------------------------------------------- utilities
__device__ __forceinline__ float tf32r(float x) {
    float h;
    asm("cvt.rna.tf32.f32 %0, %1;" : "=f"(h) : "f"(x));
    return h;
}
__device__ __forceinline__ void mma_tf32(float& d0, float& d1, float& d2, float& d3,
                                         uint32_t a0, uint32_t a1, uint32_t a2,
                                         uint32_t a3, uint32_t b0, uint32_t b1) {
    asm volatile(
        "mma.sync.aligned.m16n8k8.row.col.f32.tf32.tf32.f32 "
        "{%0,%1,%2,%3}, {%4,%5,%6,%7}, {%8,%9}, {%0,%1,%2,%3};"
        : "+f"(d0), "+f"(d1), "+f"(d2), "+f"(d3)
        : "r"(a0), "r"(a1), "r"(a2), "r"(a3), "r"(b0), "r"(b1));
}

// Reference declares int64 labels; jax w/o x64 silently yields int32. An
// int64 buffer (values 0..7, little-endian) read as int32 is [v,0,v,0,...].
__device__ __forceinline__ void load_labels(const int* __restrict__ lab32,
                                            int* lab, int* flag) {
    int t = threadIdx.x;
    if (t == 0) {
        bool is64 = true;
        for (int i = 1; i < NB; i += 2) if (lab32[i] != 0) { is64 = false; break; }
        if (is64) for (int i = 0; i < NB; i += 2) {
            int v = lab32[i];
            if (v < 0 || v >= 8) { is64 = false; break; }
        }
        *flag = is64 ? 1 : 0;
    }
    __syncthreads();
    if (t < NB) lab[t] = (*flag) ? (int)((const long long*)lab32)[t] : lab32[t];
    __syncthreads();
}

// ---- 0: prep. blocks 0..101: warp-per-row norm + tf32 hi/lo split (816 rows);
// 102..103: zero pads (rows 816..831); 104..247: pair list; 248: scalars.
__global__ void k_prep(const float* __restrict__ x, const int* __restrict__ lab32) {
    int bid = blockIdx.x, t = threadIdx.x, w = t >> 5, lane = t & 31;
    if (bid < 102) {
        int r = bid * 8 + w;             // 0..815
        const float4* src = (const float4*)&x[r * ND];
        float4 v0 = src[lane], v1 = src[lane + 32];
        float ss = v0.x*v0.x + v0.y*v0.y + v0.z*v0.z + v0.w*v0.w
                 + v1.x*v1.x + v1.y*v1.y + v1.z*v1.z + v1.w*v1.w;
        #pragma unroll
        for (int o = 16; o > 0; o >>= 1) ss += __shfl_xor_sync(0xffffffffu, ss, o);
        float inv = 1.f / fmaxf(sqrtf(ss), 1e-12f);
        int b = r / NL, p = r - b * NL;
        int row = (p == 0) ? (NM + b) : (b * (NL - 1) + p - 1);
        float4* dh = (float4*)&g_hi[row * ND];
        float4* dl = (float4*)&g_lo[row * ND];
        float4 n0 = make_float4(v0.x*inv, v0.y*inv, v0.z*inv, v0.w*inv);
        float4 n1 = make_float4(v1.x*inv, v1.y*inv, v1.z*inv, v1.w*inv);
        float4 h0 = make_float4(tf32r(n0.x), tf32r(n0.y), tf32r(n0.z), tf32r(n0.w));
        float4 h1 = make_float4(tf32r(n1.x), tf32r(n1.y), tf32r(n1.z), tf32r(n1.w));
        dh[lane]      = h0;
        dh[lane + 32] = h1;
        dl[lane]      = make_float4(tf32r(n0.x - h0.x), tf32r(n0.y - h0.y),
                                    tf32r(n0.z - h0.z), tf32r(n0.w - h0.w));
        dl[lane + 32] = make_float4(tf32r(n1.x - h1.x), tf32r(n1.y - h1.y),
                                    tf32r(n1.z - h1.z), tf32r(n1.w - h1.w));
        return;
    }
    if (bid < 104) {                     // zero pad rows 816..831
        int r = 816 + (bid - 102) * 8 + w;
        float4 z = make_float4(0.f, 0.f, 0.f, 0.f);
        float4* dh = (float4*)&g_hi[r * ND];
        float4* dl = (float4*)&g_lo[r * ND];
        dh[lane] = z; dh[lane + 32] = z;
        dl[lane] = z; dl[lane + 32] = z;
        return;
    }
    __shared__ int lab[NB];
    __shared__ int flag;
    load_labels(lab32, lab, &flag);
    if (bid < 248) {                     // pair list: ONE atomic per block
        __shared__ int wc[8];
        __shared__ unsigned base_s;
        int p = (bid - 104) * 256 + t;   // 0..36863
        int b = p / NM, j = p - b * NM;
        bool act = (lab[j >> 4] == lab[b]);
        unsigned bal = __ballot_sync(0xffffffffu, act);
        if (lane == 0) wc[w] = __popc(bal);
        __syncthreads();
        if (t == 0) {
            int tot = 0;
            #pragma unroll
            for (int i = 0; i < 8; i++) tot += wc[i];
            base_s = atomicAdd(&g_pcnt, (unsigned)tot);
        }
        __syncthreads();
        int off = 0;
        #pragma unroll
        for (int i = 0; i < 8; i++) if (i < w) off += wc[i];
        if (act)
            g_pairs[base_s + off + __popc(bal & ((1u << lane) - 1u))] = (b << 16) | j;
        return;
    }
    if (t < NB) {
        int same = 0;
        #pragma unroll 8
        for (int o = 0; o < NB; o++) same += (lab[o] == lab[t]) ? 1 : 0;
        g_lab[t]  = lab[t];
        g_nneg[t] = (float)((NB - same) * (NL - 1));
        g_P[t]    = (float)(same * (NL - 1));
    }
}

// ---- 1: symmetric GEMM via mma.sync tf32x3, exp epilogue, mirror write for
// off-diag tok tiles, fused csum on anchor-row tiles (jt==12).
// tiles: id 0..77 -> (jt,kt) upper triangle of 12x12 tok grid; 78..89 -> (12,kt)
// smem tiles stride 36 floats: fragment banks = (4n + k) mod 32, conflict-free.
__global__ void __launch_bounds__(256) k_gemm(void) {
    __shared__ __align__(16) float sbuf[4 * 64 * 36];   // Ah, Al, Bh, Bl (36.9KB)
    __shared__ int lab[NB];
    float* sAh = sbuf;
    float* sAl = sbuf + 2304;
    float* sBh = sbuf + 4608;
    float* sBl = sbuf + 6912;
    int t = threadIdx.x, w = t >> 5, lane = t & 31;
    int wr = (w & 3) * 16, wn = (w >> 2) * 32;          // warp tile: rows 16, cols 32
    if (t < NB) lab[t] = g_lab[t];

    int id = blockIdx.x, jt, kt;
    if (id < 78) {
        jt = 0; int rem = id;
        while (rem >= 12 - jt) { rem -= 12 - jt; jt++; }
        kt = jt + rem;
    } else { jt = 12; kt = id - 78; }
    int jb = jt * 64, kb = kt * 64;

    // prefetch chunk 0 (Kc = 32): 2 float4 per thread per buffer
    float4 pf[8];
    #pragma unroll
    for (int u = 0; u < 2; u++) {
        int idx = t + u * 256, row = idx >> 3, c4 = (idx & 7) * 4;
        pf[u * 4 + 0] = *(const float4*)&g_hi[(jb + row) * ND + c4];
        pf[u * 4 + 1] = *(const float4*)&g_lo[(jb + row) * ND + c4];
        pf[u * 4 + 2] = *(const float4*)&g_hi[(kb + row) * ND + c4];
        pf[u * 4 + 3] = *(const float4*)&g_lo[(kb + row) * ND + c4];
    }

    float acc[4][4] = {};                // 4 n-blocks x 4 regs (m16n8 frags)
    int ar0 = (wr + (lane >> 2)) * 36 + (lane & 3);
    for (int ch = 0; ch < 8; ch++) {
        __syncthreads();
        #pragma unroll
        for (int u = 0; u < 2; u++) {
            int idx = t + u * 256, row = idx >> 3, c4 = (idx & 7) * 4;
            *(float4*)&sAh[row * 36 + c4] = pf[u * 4 + 0];
            *(float4*)&sAl[row * 36 + c4] = pf[u * 4 + 1];
            *(float4*)&sBh[row * 36 + c4] = pf[u * 4 + 2];
            *(float4*)&sBl[row * 36 + c4] = pf[u * 4 + 3];
        }
        __syncthreads();
        if (ch < 7) {
            int k0g = (ch + 1) * 32;
            #pragma unroll
            for (int u = 0; u < 2; u++) {
                int idx = t + u * 256, row = idx >> 3, c4 = (idx & 7) * 4;
                pf[u * 4 + 0] = *(const float4*)&g_hi[(jb + row) * ND + k0g + c4];
                pf[u * 4 + 1] = *(const float4*)&g_lo[(jb + row) * ND + k0g + c4];
                pf[u * 4 + 2] = *(const float4*)&g_hi[(kb + row) * ND + k0g + c4];
                pf[u * 4 + 3] = *(const float4*)&g_lo[(kb + row) * ND + k0g + c4];
            }
        }
        #pragma unroll
        for (int ks = 0; ks < 4; ks++) {
            int k0 = ks * 8;
            uint32_t ah0 = __float_as_uint(sAh[ar0 + k0]);
            uint32_t ah1 = __float_as_uint(sAh[ar0 + 8 * 36 + k0]);
            uint32_t ah2 = __float_as_uint(sAh[ar0 + k0 + 4]);
            uint32_t ah3 = __float_as_uint(sAh[ar0 + 8 * 36 + k0 + 4]);
            uint32_t al0 = __float_as_uint(sAl[ar0 + k0]);
            uint32_t al1 = __float_as_uint(sAl[ar0 + 8 * 36 + k0]);
            uint32_t al2 = __float_as_uint(sAl[ar0 + k0 + 4]);
            uint32_t al3 = __float_as_uint(sAl[ar0 + 8 * 36 + k0 + 4]);
            #pragma unroll
            for (int nb = 0; nb < 4; nb++) {
                int br = (wn + nb * 8 + (lane >> 2)) * 36 + k0 + (lane & 3);
                uint32_t bh0 = __float_as_uint(sBh[br]);
                uint32_t bh1 = __float_as_uint(sBh[br + 4]);
                uint32_t bl0 = __float_as_uint(sBl[br]);
                uint32_t bl1 = __float_as_uint(sBl[br + 4]);
                mma_tf32(acc[nb][0], acc[nb][1], acc[nb][2], acc[nb][3],
                         ah0, ah1, ah2, ah3, bh0, bh1);
                mma_tf32(acc[nb][0], acc[nb][1], acc[nb][2], acc[nb][3],
                         ah0, ah1, ah2, ah3, bl0, bl1);
                mma_tf32(acc[nb][0], acc[nb][1], acc[nb][2], acc[nb][3],
                         al0, al1, al2, al3, bh0, bh1);
            }
        }
    }

    // stage exp(result) in Tr[64][65] (aliases sbuf: 4160 <= 9216 floats)
    __syncthreads();
    float* Tr = sbuf;
    {
        int r0 = wr + (lane >> 2), c0 = wn + 2 * (lane & 3);
        #pragma unroll
        for (int nb = 0; nb < 4; nb++) {
            int cc = c0 + nb * 8;
            Tr[r0 * 65 + cc]           = __expf(acc[nb][0]);
            Tr[r0 * 65 + cc + 1]       = __expf(acc[nb][1]);
            Tr[(r0 + 8) * 65 + cc]     = __expf(acc[nb][2]);
            Tr[(r0 + 8) * 65 + cc + 1] = __expf(acc[nb][3]);
        }
    }
    __syncthreads();

    // coalesced E write
    #pragma unroll
    for (int u = 0; u < 4; u++) {
        int idx = t + u * 256;           // 1024 float4 = 64 rows x 16
        int r = idx >> 4, c4 = (idx & 15) * 4;
        float4 v = make_float4(Tr[r*65 + c4], Tr[r*65 + c4 + 1],
                               Tr[r*65 + c4 + 2], Tr[r*65 + c4 + 3]);
        *(float4*)&g_E[(jb + r) * NM + kb + c4] = v;
    }
    if (jt < 12) {
        if (jt != kt) {                  // transpose mirror
            #pragma unroll
            for (int u = 0; u < 4; u++) {
                int idx = t + u * 256;
                int r = idx >> 4, c4 = (idx & 15) * 4;
                float4 v = make_float4(Tr[(c4+0)*65 + r], Tr[(c4+1)*65 + r],
                                       Tr[(c4+2)*65 + r], Tr[(c4+3)*65 + r]);
                *(float4*)&g_E[(kb + r) * NM + jb + c4] = v;
            }
        }
    } else if (t < NB) {                 // anchor-row tile: csum (fixed-point)
        int mb = lab[t];
        float part = 0.f;
        #pragma unroll 8
        for (int cc = 0; cc < 64; cc++)
            if (lab[(kb + cc) >> 4] != mb) part += Tr[t * 65 + cc];
        atomicAdd(&g_csum[t], (unsigned long long)(long long)llrintf(part * SCALE_C));
    }
}

// ---- 2: warp-per-pair symmetric KL (cancellation-free) + in-kernel finish
// e=c*Et, a=c*Ea, t=e-a, mu=exp(e)-1 (series), d=mu-nu=t*h (series)
// symKL = 0.5*(Sdt*D1 - Sd*N1)/(D1*D2); D1=n+Smu, N1=St+Smut, D2=D1-Sd
// Pair order is irrelevant: per-pair kl is a pure function of globals and the
// accumulation is integer fixed-point -> bit-identical across replays.
__global__ void k_pairs(float* __restrict__ out) {
    __shared__ int lab[NB];
    __shared__ unsigned int ticket_s;
    int t = threadIdx.x, lane = t & 31, w = t >> 5;
    if (t < NB) lab[t] = g_lab[t];
    __syncthreads();
    int np = (int)g_pcnt;
    for (int p = blockIdx.x * 8 + w; p < np; p += PAIR_BLOCKS * 8) {
        int pr = g_pairs[p];
        int b = pr >> 16, j = pr & 0xffff;
        int mb = lab[b];
        float c = SCALE_C / (float)(long long)g_csum[b];
        const float* Et = g_E + j * NM;
        const float* Ea = g_E + (NM + b) * NM;

        float s0 = 0.f, s1 = 0.f, s2 = 0.f, s3 = 0.f, s4 = 0.f;
        #pragma unroll
        for (int i = 0; i < 6; i++) {    // float4 per lane; 4 k share one mask
            int k4 = i * 128 + lane * 4;
            float m = (lab[k4 >> 4] != mb) ? c : 0.f;
            float4 E4 = *(const float4*)&Et[k4];
            float4 A4 = *(const float4*)&Ea[k4];
            #pragma unroll
            for (int u = 0; u < 4; u++) {
                float Ev = (u == 0) ? E4.x : (u == 1) ? E4.y : (u == 2) ? E4.z : E4.w;
                float Av = (u == 0) ? A4.x : (u == 1) ? A4.y : (u == 2) ? A4.z : A4.w;
                float e  = m * Ev;
                float a  = m * Av;
                float tt = e - a;
                float mu = e * (1.f + e * (0.5f + e * (1.f/6.f)));
                float sp = e + a;
                float e2 = e * e, ea = e * a, a2 = a * a;
                float h  = 1.f + 0.5f * sp + (e2 + ea + a2) * (1.f/6.f);
                float d  = tt * h;
                s0 += tt; s1 += mu; s2 = fmaf(mu, tt, s2);
                s3 += d;  s4 = fmaf(tt, d, s4);
            }
        }
        #pragma unroll
        for (int o = 16; o > 0; o >>= 1) {
            s0 += __shfl_down_sync(0xffffffffu, s0, o);
            s1 += __shfl_down_sync(0xffffffffu, s1, o);
            s2 += __shfl_down_sync(0xffffffffu, s2, o);
            s3 += __shfl_down_sync(0xffffffffu, s3, o);
            s4 += __shfl_down_sync(0xffffffffu, s4, o);
        }
        if (lane == 0) {
            float n  = g_nneg[b];
            float D1 = n + s1;
            float N1 = s0 + s2;
            float D2 = D1 - s3;
            float kl = 0.5f * (s4 * D1 - s3 * N1) / (D1 * D2);
            atomicAdd(&g_rowsum[b],
                      (unsigned long long)(long long)llrintf(kl * SCALE_KL));
        }
    }
    // last block: final scalar + reset all counters for the next graph replay
    __threadfence();
    __syncthreads();
    if (t == 0) ticket_s = atomicAdd(&g_done, 1u);
    __syncthreads();
    if (ticket_s == PAIR_BLOCKS - 1 && t == 0) {
        float tot = 0.f;
        for (int b = 0; b < NB; b++) {
            float rs = (float)(long long)g_rowsum[b] * (1.f / SCALE_KL);
            tot += rs / g_P[b];
            g_rowsum[b] = 0ull;
            g_csum[b]   = 0ull;
        }
        out[0] = tot / (float)NB;
        g_pcnt = 0u;
        g_done = 0u;
    }
}

// ----------------------------------------------------------------- launch
extern "C" void kernel_launch(void* const* d_in, const int* in_sizes, int n_in,
                              void* d_out, int out_size) {
    const float* x     = (const float*)d_in[0];
    const int*   lab32 = (const int*)  d_in[1];
    float*       out   = (float*)      d_out;
    (void)in_sizes; (void)n_in; (void)out_size;

    k_prep <<<PREP_BLOCKS, 256>>>(x, lab32);
    k_gemm <<<NTILES, 256>>>();
    k_pairs<<<PAIR_BLOCKS, 256>>>(out);
}